// round 4
// baseline (speedup 1.0000x reference)
#include <cuda_runtime.h>

// QConv1d via quaternion-conjugation closed form, co-invariant work shared.
// x: (B, CIN, T, 4)   out: (B, COUT, TOUT, 4)
// params packed: g_params[(co*CIN+ci)*FL+f] = {a, b, c, 0}

#define B_    2
#define CIN_  16
#define COUT_ 16
#define T_    2048
#define FL_   9
#define TOUT_ 2040
#define NQ    2                 // co per thread
#define NP    (COUT_*CIN_*FL_)  // 2304

__device__ float4 g_params[NP];

__global__ void pack_params(const float* __restrict__ pa,
                            const float* __restrict__ pb,
                            const float* __restrict__ pc)
{
    int i = blockIdx.x * blockDim.x + threadIdx.x;
    if (i < NP) g_params[i] = make_float4(pa[i], pb[i], pc[i], 0.f);
}

__global__ __launch_bounds__(512)
void qconv1d_kernel(const float* __restrict__ x, float* __restrict__ out)
{
    const int tx  = threadIdx.x;        // t within 32-tile (lane)
    const int ci  = threadIdx.y;        // input channel, one per warp
    const int t   = blockIdx.x * 32 + tx;
    const int co0 = blockIdx.y * NQ;
    const int b   = blockIdx.z;

    float aw[NQ], axv[NQ], ayv[NQ], azv[NQ];
    #pragma unroll
    for (int j = 0; j < NQ; ++j) { aw[j]=0.f; axv[j]=0.f; ayv[j]=0.f; azv[j]=0.f; }

    if (t < TOUT_) {
        const float4* xr = reinterpret_cast<const float4*>(x)
                         + ((size_t)b * CIN_ + ci) * T_ + t;
        const float4 v4 = __ldg(xr + 4);            // center tap qp
        const float pw = v4.x, vx = v4.y, vy = v4.z, vz = v4.w;
        const float vsq = vx*vx + vy*vy + vz*vz;

        const float4* pp = &g_params[(co0 * CIN_ + ci) * FL_];

        #pragma unroll
        for (int f = 0; f < FL_; ++f) {
            const float4 u4 = __ldg(xr + f);
            const float s = u4.x, ux = u4.y, uy = u4.z, uz = u4.w;
            // co-invariant rotation ingredients
            const float d   = vx*ux + vy*uy + vz*uz;
            const float d2  = d + d;
            const float crx = vy*uz - vz*uy;
            const float cry = vz*ux - vx*uz;
            const float crz = vx*uy - vy*ux;

            #pragma unroll
            for (int j = 0; j < NQ; ++j) {
                const float4 p = __ldg(pp + j * (CIN_ * FL_) + f);  // {a,b,c}
                const float w   = pw + p.z;
                const float wsq = w * w;
                const float nsq = wsq + vsq;
                const float dif = wsq - vsq;
                const float rn  = __fdividef(1.0f, nsq);
                const float w2  = w + w;

                // R = nsq * (p q p^-1): unscaled rotation, scalar pre-scaled
                const float Rx = dif*ux + d2*vx + w2*crx;
                const float Ry = dif*uy + d2*vy + w2*cry;
                const float Rz = dif*uz + d2*vz + w2*crz;
                const float Rw = nsq * s;

                // (q + b e) (x) R   — equals nsq * true result
                const float qw2 = s + p.y;
                const float ow = qw2*Rw - ux*Rx - uy*Ry - uz*Rz;
                const float ox = qw2*Rx + ux*Rw + uy*Rz - uz*Ry;
                const float oy = qw2*Ry - ux*Rz + uy*Rw + uz*Rx;
                const float oz = qw2*Rz + ux*Ry - uy*Rx + uz*Rw;

                const float arn = p.x * rn;          // a / nsq
                aw[j]  = fmaf(arn, ow, aw[j]);
                axv[j] = fmaf(arn, ox, axv[j]);
                ayv[j] = fmaf(arn, oy, ayv[j]);
                azv[j] = fmaf(arn, oz, azv[j]);
            }
        }
    }

    // tree-reduce over the 16 ci groups (threadIdx.y)
    __shared__ float4 red[8][32][NQ];
    #pragma unroll
    for (int off = 8; off > 0; off >>= 1) {
        if (ci >= off && ci < 2 * off) {
            #pragma unroll
            for (int j = 0; j < NQ; ++j)
                red[ci - off][tx][j] = make_float4(aw[j], axv[j], ayv[j], azv[j]);
        }
        __syncthreads();
        if (ci < off) {
            #pragma unroll
            for (int j = 0; j < NQ; ++j) {
                const float4 r = red[ci][tx][j];
                aw[j] += r.x; axv[j] += r.y; ayv[j] += r.z; azv[j] += r.w;
            }
        }
        __syncthreads();
    }

    if (ci == 0 && t < TOUT_) {
        #pragma unroll
        for (int j = 0; j < NQ; ++j) {
            reinterpret_cast<float4*>(out)[((size_t)b * COUT_ + co0 + j) * TOUT_ + t]
                = make_float4(aw[j], axv[j], ayv[j], azv[j]);
        }
    }
}

extern "C" void kernel_launch(void* const* d_in, const int* in_sizes, int n_in,
                              void* d_out, int out_size)
{
    const float* x  = (const float*)d_in[0];
    const float* pa = (const float*)d_in[1];
    const float* pb = (const float*)d_in[2];
    const float* pc = (const float*)d_in[3];
    float* out = (float*)d_out;

    pack_params<<<(NP + 255) / 256, 256>>>(pa, pb, pc);

    dim3 block(32, CIN_, 1);
    dim3 grid((TOUT_ + 31) / 32, COUT_ / NQ, B_);
    qconv1d_kernel<<<grid, block>>>(x, out);
}

// round 5
// speedup vs baseline: 1.0894x; 1.0894x over previous
#include <cuda_runtime.h>

// QConv1d via quaternion-conjugation closed form (single kernel).
// x: (B, CIN, T, 4)   a,b,c: (COUT, CIN, FL)   out: (B, COUT, TOUT, 4)

#define B_    2
#define CIN_  16
#define COUT_ 16
#define T_    2048
#define FL_   9
#define TOUT_ 2040
#define NQ    2                 // co per thread

__global__ __launch_bounds__(32 * CIN_)
void qconv1d_kernel(const float* __restrict__ x,
                    const float* __restrict__ pa,
                    const float* __restrict__ pb,
                    const float* __restrict__ pc,
                    float* __restrict__ out)
{
    __shared__ float4 sp[NQ][CIN_][FL_];          // {a,b,c,-} per (co,ci,f)
    __shared__ float4 red[CIN_ - 1][32][NQ];

    const int tx  = threadIdx.x;
    const int ci  = threadIdx.y;
    const int tid = ci * 32 + tx;
    const int t   = blockIdx.x * 32 + tx;
    const int co0 = blockIdx.y * NQ;
    const int b   = blockIdx.z;

    // cooperative param pack into smem (288 entries, 512 threads)
    if (tid < NQ * CIN_ * FL_) {
        const int j   = tid / (CIN_ * FL_);
        const int rem = tid % (CIN_ * FL_);
        const int cci = rem / FL_;
        const int f   = rem % FL_;
        const int src = ((co0 + j) * CIN_ + cci) * FL_ + f;
        sp[j][cci][f] = make_float4(__ldg(pa + src), __ldg(pb + src), __ldg(pc + src), 0.f);
    }
    __syncthreads();

    float aw[NQ], axv[NQ], ayv[NQ], azv[NQ];
    #pragma unroll
    for (int j = 0; j < NQ; ++j) { aw[j]=0.f; axv[j]=0.f; ayv[j]=0.f; azv[j]=0.f; }

    if (t < TOUT_) {
        const float4* xr = reinterpret_cast<const float4*>(x)
                         + ((size_t)b * CIN_ + ci) * T_ + t;
        const float4 v4 = __ldg(xr + 4);           // center tap qp
        const float pw = v4.x, vx = v4.y, vy = v4.z, vz = v4.w;
        const float vsq  = vx*vx + vy*vy + vz*vz;
        const float nvsq = -vsq;

        #pragma unroll
        for (int f = 0; f < FL_; ++f) {
            const float4 u4 = __ldg(xr + f);
            const float s = u4.x, ux = u4.y, uy = u4.z, uz = u4.w;

            // co-invariant: R(w) = w^2*u + w*(2 v x u) + (2d v - vsq u)
            const float d    = vx*ux + vy*uy + vz*uz;
            const float d2   = d + d;
            float crx = vy*uz - vz*uy;  crx += crx;
            float cry = vz*ux - vx*uz;  cry += cry;
            float crz = vx*uy - vy*ux;  crz += crz;
            const float a0x = fmaf(d2, vx, nvsq * ux);
            const float a0y = fmaf(d2, vy, nvsq * uy);
            const float a0z = fmaf(d2, vz, nvsq * uz);

            #pragma unroll
            for (int j = 0; j < NQ; ++j) {
                const float4 p  = sp[j][ci][f];     // {a,b,c}
                const float w   = pw + p.z;
                const float wsq = w * w;
                const float nsq = wsq + vsq;
                const float rn  = __fdividef(1.0f, nsq);
                const float arn = p.x * rn;

                // pre-scaled rotation: a/nsq * (nsq * rotated-vector); scalar = s*a
                const float Rx = fmaf(w, fmaf(w, ux, crx), a0x) * arn;
                const float Ry = fmaf(w, fmaf(w, uy, cry), a0y) * arn;
                const float Rz = fmaf(w, fmaf(w, uz, crz), a0z) * arn;
                const float Rw = s * p.x;

                // acc += (q + b e) (x) R   (FMA directly into accumulators)
                const float qw2 = s + p.y;
                aw[j]  = fmaf(qw2, Rw, aw[j]);
                aw[j]  = fmaf(-ux, Rx, aw[j]);
                aw[j]  = fmaf(-uy, Ry, aw[j]);
                aw[j]  = fmaf(-uz, Rz, aw[j]);
                axv[j] = fmaf(qw2, Rx, axv[j]);
                axv[j] = fmaf( ux, Rw, axv[j]);
                axv[j] = fmaf( uy, Rz, axv[j]);
                axv[j] = fmaf(-uz, Ry, axv[j]);
                ayv[j] = fmaf(qw2, Ry, ayv[j]);
                ayv[j] = fmaf(-ux, Rz, ayv[j]);
                ayv[j] = fmaf( uy, Rw, ayv[j]);
                ayv[j] = fmaf( uz, Rx, ayv[j]);
                azv[j] = fmaf(qw2, Rz, azv[j]);
                azv[j] = fmaf( ux, Ry, azv[j]);
                azv[j] = fmaf(-uy, Rx, azv[j]);
                azv[j] = fmaf( uz, Rw, azv[j]);
            }
        }
    }

    // flat reduction over 16 ci warps: one store + one barrier + warp-0 sum
    if (ci > 0) {
        #pragma unroll
        for (int j = 0; j < NQ; ++j)
            red[ci - 1][tx][j] = make_float4(aw[j], axv[j], ayv[j], azv[j]);
    }
    __syncthreads();
    if (ci == 0 && t < TOUT_) {
        #pragma unroll
        for (int j = 0; j < NQ; ++j) {
            #pragma unroll
            for (int k = 0; k < CIN_ - 1; ++k) {
                const float4 r = red[k][tx][j];
                aw[j] += r.x; axv[j] += r.y; ayv[j] += r.z; azv[j] += r.w;
            }
            reinterpret_cast<float4*>(out)[((size_t)b * COUT_ + co0 + j) * TOUT_ + t]
                = make_float4(aw[j], axv[j], ayv[j], azv[j]);
        }
    }
}

extern "C" void kernel_launch(void* const* d_in, const int* in_sizes, int n_in,
                              void* d_out, int out_size)
{
    const float* x  = (const float*)d_in[0];
    const float* pa = (const float*)d_in[1];
    const float* pb = (const float*)d_in[2];
    const float* pc = (const float*)d_in[3];
    float* out = (float*)d_out;

    dim3 block(32, CIN_, 1);
    dim3 grid((TOUT_ + 31) / 32, COUT_ / NQ, B_);
    qconv1d_kernel<<<grid, block>>>(x, pa, pb, pc, out);
}